// round 1
// baseline (speedup 1.0000x reference)
#include <cuda_runtime.h>
#include <cstdint>

// ---------------------------------------------------------------------------
// GCN layer: h = x @ W + b  ->  agg = SpMM(adj, h)  ->  PReLU(agg)
// N=100000 nodes, IN=128, OUT=64, E=1.6M edges.
// Scratch for h lives in a __device__ global (no allocations allowed).
// ---------------------------------------------------------------------------

#define IN_FT  128
#define OUT_FT 64
#define N_CAP  100096   // >= N, padded

static __device__ float g_h[(size_t)N_CAP * OUT_FT];

// ---------------------------------------------------------------------------
// Kernel 0: zero the output accumulator (float4 stores)
// ---------------------------------------------------------------------------
__global__ void zero_kernel(float4* __restrict__ out, int n4) {
    int i = blockIdx.x * blockDim.x + threadIdx.x;
    if (i < n4) out[i] = make_float4(0.f, 0.f, 0.f, 0.f);
}

// ---------------------------------------------------------------------------
// Kernel 1: GEMM h[N,64] = x[N,128] @ W[128,64] + b[64]
// Tile: 64 rows per block, full K=128, full N=64.
// X tile staged in shared (padded rows, conflict-free), W read through L1
// (32KB, resident + reused by every block). 256 threads, 4x4 microtile each.
// ---------------------------------------------------------------------------
__global__ __launch_bounds__(256, 4)
void gemm_kernel(const float* __restrict__ x,
                 const float* __restrict__ W,
                 const float* __restrict__ b,
                 int N) {
    __shared__ float Xs[64 * 132];   // 132-float row pitch -> bank-spread

    const int tid  = threadIdx.x;
    const int row0 = blockIdx.x * 64;

    // Stage X tile: 64 rows x 128 floats. 32 threads per row (float4 each),
    // 8 rows per pass, 8 passes. Guard rows >= N with zeros.
    {
        const int r  = tid >> 5;        // 0..7
        const int c4 = tid & 31;        // float4 index in row (0..31)
        #pragma unroll
        for (int p = 0; p < 8; p++) {
            const int rr   = r + p * 8;
            const int grow = row0 + rr;
            float4 v = make_float4(0.f, 0.f, 0.f, 0.f);
            if (grow < N)
                v = reinterpret_cast<const float4*>(x + (size_t)grow * IN_FT)[c4];
            *reinterpret_cast<float4*>(&Xs[rr * 132 + c4 * 4]) = v;
        }
    }
    __syncthreads();

    const int tx = tid & 15;   // col group: cols [tx*4, tx*4+4)
    const int ty = tid >> 4;   // row group: rows [ty*4, ty*4+4)

    float acc[4][4];
    #pragma unroll
    for (int i = 0; i < 4; i++)
        #pragma unroll
        for (int j = 0; j < 4; j++) acc[i][j] = 0.f;

    const float4* __restrict__ Wg = reinterpret_cast<const float4*>(W);

    #pragma unroll 8
    for (int k = 0; k < IN_FT; k++) {
        const float4 w4 = __ldg(&Wg[k * 16 + tx]);   // W[k][tx*4 .. +3], L1-hit
        float xf[4];
        #pragma unroll
        for (int i = 0; i < 4; i++)
            xf[i] = Xs[(ty * 4 + i) * 132 + k];
        #pragma unroll
        for (int i = 0; i < 4; i++) {
            acc[i][0] = fmaf(xf[i], w4.x, acc[i][0]);
            acc[i][1] = fmaf(xf[i], w4.y, acc[i][1]);
            acc[i][2] = fmaf(xf[i], w4.z, acc[i][2]);
            acc[i][3] = fmaf(xf[i], w4.w, acc[i][3]);
        }
    }

    // Epilogue: add bias, store float4 to g_h
    const float4 bv = __ldg(reinterpret_cast<const float4*>(b) + tx);
    #pragma unroll
    for (int i = 0; i < 4; i++) {
        const int r = row0 + ty * 4 + i;
        if (r < N) {
            float4 o;
            o.x = acc[i][0] + bv.x;
            o.y = acc[i][1] + bv.y;
            o.z = acc[i][2] + bv.z;
            o.w = acc[i][3] + bv.w;
            reinterpret_cast<float4*>(g_h + (size_t)r * OUT_FT)[tx] = o;
        }
    }
}

// ---------------------------------------------------------------------------
// Kernel 2: SpMM scatter. 16 threads per edge, float4 per thread.
// out[row] += val * h[col]  via red.global.add.v4.f32 (vectorized reduction,
// no return value -> best L2-atomic throughput path).
// ---------------------------------------------------------------------------
__global__ __launch_bounds__(256)
void spmm_kernel(const int*   __restrict__ erow,
                 const int*   __restrict__ ecol,
                 const float* __restrict__ eval,
                 float*       __restrict__ out,
                 int E) {
    const int e = blockIdx.x * 16 + (threadIdx.x >> 4);
    if (e >= E) return;
    const int l16 = threadIdx.x & 15;

    const int   row = erow[e];
    const int   col = ecol[e];
    const float val = eval[e];

    const float4 hv =
        reinterpret_cast<const float4*>(g_h)[(size_t)col * (OUT_FT / 4) + l16];

    const float a = hv.x * val;
    const float bq = hv.y * val;
    const float c = hv.z * val;
    const float d = hv.w * val;

    float* dst = out + (size_t)row * OUT_FT + l16 * 4;
    asm volatile("red.global.add.v4.f32 [%0], {%1, %2, %3, %4};"
                 :: "l"(dst), "f"(a), "f"(bq), "f"(c), "f"(d)
                 : "memory");
}

// ---------------------------------------------------------------------------
// Kernel 3: PReLU in place, shared scalar slope
// ---------------------------------------------------------------------------
__global__ void prelu_kernel(float4* __restrict__ out,
                             const float* __restrict__ alpha, int n4) {
    const int i = blockIdx.x * blockDim.x + threadIdx.x;
    if (i >= n4) return;
    const float a = __ldg(alpha);
    float4 v = out[i];
    v.x = v.x >= 0.f ? v.x : a * v.x;
    v.y = v.y >= 0.f ? v.y : a * v.y;
    v.z = v.z >= 0.f ? v.z : a * v.z;
    v.w = v.w >= 0.f ? v.w : a * v.w;
    out[i] = v;
}

// ---------------------------------------------------------------------------
// Launch
// Inputs (metadata order): x, W, b, alpha, edge_row, edge_col, edge_val
// ---------------------------------------------------------------------------
extern "C" void kernel_launch(void* const* d_in, const int* in_sizes, int n_in,
                              void* d_out, int out_size) {
    const float* x     = (const float*)d_in[0];
    const float* W     = (const float*)d_in[1];
    const float* b     = (const float*)d_in[2];
    const float* alpha = (const float*)d_in[3];
    const int*   erow  = (const int*)  d_in[4];
    const int*   ecol  = (const int*)  d_in[5];
    const float* eval  = (const float*)d_in[6];

    const int N = in_sizes[0] / IN_FT;
    const int E = in_sizes[4];
    float* out = (float*)d_out;

    const int n4 = out_size / 4;   // float4 count of output

    zero_kernel<<<(n4 + 255) / 256, 256>>>(reinterpret_cast<float4*>(out), n4);
    gemm_kernel<<<(N + 63) / 64, 256>>>(x, W, b, N);
    spmm_kernel<<<(E + 15) / 16, 256>>>(erow, ecol, eval, out, E);
    prelu_kernel<<<(n4 + 255) / 256, 256>>>(reinterpret_cast<float4*>(out), alpha, n4);
}

// round 2
// speedup vs baseline: 1.0243x; 1.0243x over previous
#include <cuda_runtime.h>
#include <cstdint>

// ---------------------------------------------------------------------------
// GCN layer on GB300:
//   h = x @ W + b          (FFMA2-packed fp32 GEMM)
//   CSR build in-kernel    (hist -> scan -> permute)
//   agg = SpMM(adj, h)     (warp-per-row gather, L2-resident h)
//   PReLU fused into SpMM epilogue
// N=100000, IN=128, OUT=64, E=1.6M
// ---------------------------------------------------------------------------

#define IN_FT   128
#define OUT_FT  64
#define N_CAP   131072
#define E_CAP   1605632

typedef unsigned long long u64;

static __device__ float g_h[(size_t)N_CAP * OUT_FT];   // 33.5MB scratch (h)
static __device__ int   g_cnt[N_CAP + 1];
static __device__ int   g_rs[N_CAP + 1];               // row_start
static __device__ int   g_cur[N_CAP];                  // scatter cursors
static __device__ int2  g_pairs[E_CAP];                // CSR (col, val-bits)
static __device__ int   g_part[512];                   // scan partials

// ---- packed fp32x2 helpers -------------------------------------------------
__device__ __forceinline__ u64 pack2(float lo, float hi) {
    u64 r;
    asm("mov.b64 %0, {%1, %2};" : "=l"(r) : "f"(lo), "f"(hi));
    return r;
}
__device__ __forceinline__ float2 unpack2(u64 v) {
    float2 r;
    asm("mov.b64 {%0, %1}, %2;" : "=f"(r.x), "=f"(r.y) : "l"(v));
    return r;
}
__device__ __forceinline__ u64 fma2(u64 a, u64 b, u64 c) {
    u64 d;
    asm("fma.rn.f32x2 %0, %1, %2, %3;" : "=l"(d) : "l"(a), "l"(b), "l"(c));
    return d;
}

// ---------------------------------------------------------------------------
// GEMM: h[N,64] = x[N,128] @ W[128,64] + b
// 128 threads/block, 64-row tile. Microtile 4 rows x 8 cols per thread,
// cols packed in f32x2 pairs -> 16 FFMA2 per 2-k step per thread.
// ---------------------------------------------------------------------------
#define XP 132   // Xs row pitch (floats): 16B-aligned stores, 2-way-max LDS

__global__ __launch_bounds__(128)
void gemm_kernel(const float* __restrict__ x,
                 const float* __restrict__ W,
                 const float* __restrict__ b,
                 int N) {
    __shared__ float Xs[64 * XP];

    const int tid  = threadIdx.x;
    const int row0 = blockIdx.x * 64;

    // Stage X tile: 32 lanes (float4) per row, 4 rows per pass, 16 passes
    {
        const int c4 = tid & 31;
        const int r  = tid >> 5;
        #pragma unroll
        for (int p = 0; p < 16; p++) {
            const int rr   = r + p * 4;
            const int grow = row0 + rr;
            float4 v = make_float4(0.f, 0.f, 0.f, 0.f);
            if (grow < N)
                v = reinterpret_cast<const float4*>(x + (size_t)grow * IN_FT)[c4];
            *reinterpret_cast<float4*>(&Xs[rr * XP + c4 * 4]) = v;
        }
    }
    __syncthreads();

    const int tx = tid & 7;    // col group: cols [tx*8, tx*8+8)
    const int ty = tid >> 3;   // row group: rows [ty*4, ty*4+4)

    u64 acc[4][4];
    #pragma unroll
    for (int i = 0; i < 4; i++)
        #pragma unroll
        for (int j = 0; j < 4; j++) acc[i][j] = 0ULL;

    const float4* __restrict__ Wg = reinterpret_cast<const float4*>(W);

    #pragma unroll 4
    for (int k = 0; k < IN_FT; k += 2) {
        const float4 wa0 = __ldg(&Wg[(k    ) * 16 + tx * 2    ]);
        const float4 wb0 = __ldg(&Wg[(k    ) * 16 + tx * 2 + 1]);
        const float4 wa1 = __ldg(&Wg[(k + 1) * 16 + tx * 2    ]);
        const float4 wb1 = __ldg(&Wg[(k + 1) * 16 + tx * 2 + 1]);
        u64 w0[4], w1[4];
        w0[0] = pack2(wa0.x, wa0.y); w0[1] = pack2(wa0.z, wa0.w);
        w0[2] = pack2(wb0.x, wb0.y); w0[3] = pack2(wb0.z, wb0.w);
        w1[0] = pack2(wa1.x, wa1.y); w1[1] = pack2(wa1.z, wa1.w);
        w1[2] = pack2(wb1.x, wb1.y); w1[3] = pack2(wb1.z, wb1.w);

        #pragma unroll
        for (int i = 0; i < 4; i++) {
            const float2 xv = *reinterpret_cast<const float2*>(
                                  &Xs[(ty * 4 + i) * XP + k]);
            const u64 x0 = pack2(xv.x, xv.x);
            const u64 x1 = pack2(xv.y, xv.y);
            #pragma unroll
            for (int j = 0; j < 4; j++) {
                acc[i][j] = fma2(x0, w0[j], acc[i][j]);
                acc[i][j] = fma2(x1, w1[j], acc[i][j]);
            }
        }
    }

    const float4 bv0 = __ldg(reinterpret_cast<const float4*>(b) + tx * 2);
    const float4 bv1 = __ldg(reinterpret_cast<const float4*>(b) + tx * 2 + 1);

    #pragma unroll
    for (int i = 0; i < 4; i++) {
        const int r = row0 + ty * 4 + i;
        if (r < N) {
            const float2 p0 = unpack2(acc[i][0]);
            const float2 p1 = unpack2(acc[i][1]);
            const float2 p2 = unpack2(acc[i][2]);
            const float2 p3 = unpack2(acc[i][3]);
            float4 o0, o1;
            o0.x = p0.x + bv0.x; o0.y = p0.y + bv0.y;
            o0.z = p1.x + bv0.z; o0.w = p1.y + bv0.w;
            o1.x = p2.x + bv1.x; o1.y = p2.y + bv1.y;
            o1.z = p3.x + bv1.z; o1.w = p3.y + bv1.w;
            float4* dst = reinterpret_cast<float4*>(g_h + (size_t)r * OUT_FT + tx * 8);
            dst[0] = o0;
            dst[1] = o1;
        }
    }
}

// ---------------------------------------------------------------------------
// CSR build
// ---------------------------------------------------------------------------
__global__ void zero_cnt_kernel(int n) {
    int i = blockIdx.x * blockDim.x + threadIdx.x;
    if (i < n) g_cnt[i] = 0;
}

__global__ void hist_kernel(const int* __restrict__ erow, int E) {
    int e = blockIdx.x * blockDim.x + threadIdx.x;
    if (e < E) atomicAdd(&g_cnt[erow[e]], 1);
}

// per-256-block sums of g_cnt
__global__ void scan_part_kernel(int N) {
    __shared__ int s[256];
    const int tid = threadIdx.x;
    const int idx = blockIdx.x * 256 + tid;
    int v = (idx < N) ? g_cnt[idx] : 0;
    s[tid] = v;
    __syncthreads();
    #pragma unroll
    for (int off = 128; off > 0; off >>= 1) {
        if (tid < off) s[tid] += s[tid + off];
        __syncthreads();
    }
    if (tid == 0) g_part[blockIdx.x] = s[0];
}

// single-block exclusive scan of the partials
__global__ void scan_single_kernel(int NB, int E, int N) {
    __shared__ int s[512];
    const int tid = threadIdx.x;
    int v = (tid < NB) ? g_part[tid] : 0;
    s[tid] = v;
    __syncthreads();
    #pragma unroll
    for (int off = 1; off < 512; off <<= 1) {
        int t = (tid >= off) ? s[tid - off] : 0;
        __syncthreads();
        s[tid] += t;
        __syncthreads();
    }
    if (tid < NB) g_part[tid] = s[tid] - v;   // exclusive
    if (tid == 0) { g_rs[N] = E; }
}

// blockwise exclusive scan of g_cnt + partial offset -> row_start, cursors
__global__ void scan_final_kernel(int N) {
    __shared__ int s[256];
    const int tid = threadIdx.x;
    const int idx = blockIdx.x * 256 + tid;
    const int v = (idx < N) ? g_cnt[idx] : 0;
    s[tid] = v;
    __syncthreads();
    #pragma unroll
    for (int off = 1; off < 256; off <<= 1) {
        int t = (tid >= off) ? s[tid - off] : 0;
        __syncthreads();
        s[tid] += t;
        __syncthreads();
    }
    if (idx < N) {
        const int excl = s[tid] - v + g_part[blockIdx.x];
        g_rs[idx]  = excl;
        g_cur[idx] = excl;
    }
}

__global__ void scatter_kernel(const int*   __restrict__ erow,
                               const int*   __restrict__ ecol,
                               const float* __restrict__ eval,
                               int E) {
    int e = blockIdx.x * blockDim.x + threadIdx.x;
    if (e >= E) return;
    const int row = erow[e];
    const int p   = atomicAdd(&g_cur[row], 1);
    g_pairs[p] = make_int2(ecol[e], __float_as_int(eval[e]));
}

// ---------------------------------------------------------------------------
// SpMM gather + fused PReLU: one warp per row.
// Lane owns output cols (2*lane, 2*lane+1) -> one LDG.64 per edge per lane.
// Edge (col,val) pairs broadcast via shuffles.
// ---------------------------------------------------------------------------
__global__ __launch_bounds__(256)
void spmm_gather_kernel(float* __restrict__ out,
                        const float* __restrict__ alpha,
                        int N) {
    const int lane = threadIdx.x & 31;
    const int row  = blockIdx.x * 8 + (threadIdx.x >> 5);
    if (row >= N) return;

    const int start = g_rs[row];
    const int end   = g_rs[row + 1];

    float2 acc = make_float2(0.f, 0.f);
    const float2* __restrict__ h2 = reinterpret_cast<const float2*>(g_h);

    for (int base = start; base < end; base += 32) {
        const int m = min(32, end - base);
        int2 pr = make_int2(0, 0);
        if (lane < m) pr = g_pairs[base + lane];
        for (int j = 0; j < m; j++) {
            const int   col = __shfl_sync(0xffffffffu, pr.x, j);
            const float val = __int_as_float(__shfl_sync(0xffffffffu, pr.y, j));
            const float2 hv = __ldg(&h2[(size_t)col * (OUT_FT / 2) + lane]);
            acc.x = fmaf(val, hv.x, acc.x);
            acc.y = fmaf(val, hv.y, acc.y);
        }
    }

    const float a = __ldg(alpha);
    acc.x = acc.x >= 0.f ? acc.x : a * acc.x;
    acc.y = acc.y >= 0.f ? acc.y : a * acc.y;
    reinterpret_cast<float2*>(out)[(size_t)row * (OUT_FT / 2) + lane] = acc;
}

// ---------------------------------------------------------------------------
// Launch. Inputs: x, W, b, alpha, edge_row, edge_col, edge_val
// ---------------------------------------------------------------------------
extern "C" void kernel_launch(void* const* d_in, const int* in_sizes, int n_in,
                              void* d_out, int out_size) {
    const float* x     = (const float*)d_in[0];
    const float* W     = (const float*)d_in[1];
    const float* b     = (const float*)d_in[2];
    const float* alpha = (const float*)d_in[3];
    const int*   erow  = (const int*)  d_in[4];
    const int*   ecol  = (const int*)  d_in[5];
    const float* eval  = (const float*)d_in[6];

    const int N  = in_sizes[0] / IN_FT;
    const int E  = in_sizes[4];
    const int NB = (N + 255) / 256;       // <= 512 required by scan_single
    float* out = (float*)d_out;

    gemm_kernel<<<(N + 63) / 64, 128>>>(x, W, b, N);

    zero_cnt_kernel<<<(N + 256) / 256, 256>>>(N + 1);
    hist_kernel<<<(E + 255) / 256, 256>>>(erow, E);
    scan_part_kernel<<<NB, 256>>>(N);
    scan_single_kernel<<<1, 512>>>(NB, E, N);
    scan_final_kernel<<<NB, 256>>>(N);
    scatter_kernel<<<(E + 255) / 256, 256>>>(erow, ecol, eval, E);

    spmm_gather_kernel<<<(N + 7) / 8, 256>>>(out, alpha, N);
}

// round 3
// speedup vs baseline: 1.2187x; 1.1898x over previous
#include <cuda_runtime.h>
#include <cstdint>

// ---------------------------------------------------------------------------
// GCN layer on GB300 (sm_103a), 5-kernel pipeline:
//  K1 gemm+hist : h = xW + b  (row-pair FFMA2, transposed X in smem)
//                 + edge histogram fused at tail
//  K2 scanB     : per-256-block exclusive scan of counts; zero cursors;
//                 reset counts (invariant: g_cnt==0 at every call entry)
//  K3 scanP     : single-block exclusive scan of 391 partials
//  K4 scatter   : permute edges into CSR pair array
//  K5 gather    : warp-per-row SpMM gather + fused PReLU
// ---------------------------------------------------------------------------

#define IN_FT   128
#define OUT_FT  64
#define N_CAP   131072
#define E_CAP   1605632
#define NB_CAP  512

typedef unsigned long long u64;

static __device__ float g_h[(size_t)N_CAP * OUT_FT];
static __device__ int   g_cnt[N_CAP + 2];   // zero at entry (reset by scanB)
static __device__ int   g_lex[N_CAP + 2];   // block-local exclusive scan
static __device__ int   g_cur[N_CAP];       // scatter cursors (zeroed by scanB)
static __device__ int   g_part[NB_CAP];     // per-block sums -> exclusive scan
static __device__ int2  g_pairs[E_CAP];     // CSR (col, val bits)

// ---- packed fp32x2 helpers -------------------------------------------------
__device__ __forceinline__ u64 pack2(float lo, float hi) {
    u64 r;
    asm("mov.b64 %0, {%1, %2};" : "=l"(r) : "f"(lo), "f"(hi));
    return r;
}
__device__ __forceinline__ float2 unpack2(u64 v) {
    float2 r;
    asm("mov.b64 {%0, %1}, %2;" : "=f"(r.x), "=f"(r.y) : "l"(v));
    return r;
}
__device__ __forceinline__ u64 fma2(u64 a, u64 b, u64 c) {
    u64 d;
    asm("fma.rn.f32x2 %0, %1, %2, %3;" : "=l"(d) : "l"(a), "l"(b), "l"(c));
    return d;
}

// ---------------------------------------------------------------------------
// K1: GEMM (64-row tile, 128 threads) + fused histogram.
// Xs transposed: Xs[k*64 + row]. Thread = 4 row-pairs (8 rows) x 4 cols.
// acc[i][j] packs (row ty*8+2i, row ty*8+2i+1) for col 4*tx+j.
// ---------------------------------------------------------------------------
__global__ __launch_bounds__(128)
void gemm_hist_kernel(const float* __restrict__ x,
                      const float* __restrict__ W,
                      const float* __restrict__ b,
                      const int*   __restrict__ erow,
                      int N, int E) {
    __shared__ float Xs[IN_FT * 64];   // 32 KB, [k][row]

    const int tid  = threadIdx.x;
    const int row0 = blockIdx.x * 64;

    // Stage transposed X tile. Thread handles row (tid&63), float4-col
    // group (tid>>6)*16 + p. STS pattern is conflict-free (bank = row mod 32).
    {
        const int r    = tid & 63;
        const int grow = row0 + r;
        const int c4b  = (tid >> 6) * 16;
        const bool ok  = (grow < N);
        const float4* xr = reinterpret_cast<const float4*>(x + (size_t)grow * IN_FT);
        #pragma unroll
        for (int p = 0; p < 16; p++) {
            const int c4 = c4b + p;
            float4 v = make_float4(0.f, 0.f, 0.f, 0.f);
            if (ok) v = xr[c4];
            Xs[(c4 * 4 + 0) * 64 + r] = v.x;
            Xs[(c4 * 4 + 1) * 64 + r] = v.y;
            Xs[(c4 * 4 + 2) * 64 + r] = v.z;
            Xs[(c4 * 4 + 3) * 64 + r] = v.w;
        }
    }
    __syncthreads();

    const int tx = tid & 15;   // cols [4*tx, 4*tx+4)
    const int ty = tid >> 4;   // rows [ty*8, ty*8+8) as 4 pairs

    u64 acc[4][4];
    #pragma unroll
    for (int i = 0; i < 4; i++)
        #pragma unroll
        for (int j = 0; j < 4; j++) acc[i][j] = 0ULL;

    const float4* __restrict__ Wg = reinterpret_cast<const float4*>(W);

    #pragma unroll 4
    for (int k = 0; k < IN_FT; k++) {
        const float4 w = __ldg(&Wg[k * 16 + tx]);
        u64 wd[4];
        wd[0] = pack2(w.x, w.x);
        wd[1] = pack2(w.y, w.y);
        wd[2] = pack2(w.z, w.z);
        wd[3] = pack2(w.w, w.w);

        const u64* xr = reinterpret_cast<const u64*>(&Xs[k * 64 + ty * 8]);
        u64 xp[4];
        xp[0] = xr[0]; xp[1] = xr[1]; xp[2] = xr[2]; xp[3] = xr[3];

        #pragma unroll
        for (int i = 0; i < 4; i++)
            #pragma unroll
            for (int j = 0; j < 4; j++)
                acc[i][j] = fma2(xp[i], wd[j], acc[i][j]);
    }

    // Epilogue: unpack row pairs, add bias, store float4 per row.
    const float4 bv = __ldg(reinterpret_cast<const float4*>(b) + tx);
    #pragma unroll
    for (int i = 0; i < 4; i++) {
        const float2 c0 = unpack2(acc[i][0]);
        const float2 c1 = unpack2(acc[i][1]);
        const float2 c2 = unpack2(acc[i][2]);
        const float2 c3 = unpack2(acc[i][3]);
        const int r0 = row0 + ty * 8 + 2 * i;
        if (r0 < N) {
            float4 o;
            o.x = c0.x + bv.x; o.y = c1.x + bv.y;
            o.z = c2.x + bv.z; o.w = c3.x + bv.w;
            *reinterpret_cast<float4*>(g_h + (size_t)r0 * OUT_FT + tx * 4) = o;
        }
        if (r0 + 1 < N) {
            float4 o;
            o.x = c0.y + bv.x; o.y = c1.y + bv.y;
            o.z = c2.y + bv.z; o.w = c3.y + bv.w;
            *reinterpret_cast<float4*>(g_h + (size_t)(r0 + 1) * OUT_FT + tx * 4) = o;
        }
    }

    // Fused histogram (g_cnt is zero at call entry).
    const int stride = gridDim.x * 128;
    for (int e = blockIdx.x * 128 + tid; e < E; e += stride)
        atomicAdd(&g_cnt[__ldg(&erow[e])], 1);
}

// ---------------------------------------------------------------------------
// K2: block-level exclusive scan of counts. Writes g_lex (idx<=N), zeroes
// cursors, resets g_cnt, emits block totals to g_part.
// ---------------------------------------------------------------------------
__global__ __launch_bounds__(256)
void scanB_kernel(int N) {
    __shared__ int s[256];
    const int tid = threadIdx.x;
    const int idx = blockIdx.x * 256 + tid;

    const int v = (idx < N) ? g_cnt[idx] : 0;
    s[tid] = v;
    __syncthreads();
    #pragma unroll
    for (int off = 1; off < 256; off <<= 1) {
        const int t = (tid >= off) ? s[tid - off] : 0;
        __syncthreads();
        s[tid] += t;
        __syncthreads();
    }
    g_lex[idx] = s[tid] - v;            // exclusive (valid for idx<=N)
    if (idx < N) {
        g_cur[idx] = 0;
        g_cnt[idx] = 0;                 // restore invariant for next call
    }
    if (tid == 255) g_part[blockIdx.x] = s[255];
}

// ---------------------------------------------------------------------------
// K3: single-block exclusive scan of g_part[0..NB)
// ---------------------------------------------------------------------------
__global__ void scanP_kernel(int NB) {
    __shared__ int s[NB_CAP];
    const int tid = threadIdx.x;
    const int v = (tid < NB) ? g_part[tid] : 0;
    s[tid] = v;
    __syncthreads();
    #pragma unroll
    for (int off = 1; off < NB_CAP; off <<= 1) {
        const int t = (tid >= off) ? s[tid - off] : 0;
        __syncthreads();
        s[tid] += t;
        __syncthreads();
    }
    if (tid < NB) g_part[tid] = s[tid] - v;
}

// ---------------------------------------------------------------------------
// K4: scatter edges into CSR pair array
// ---------------------------------------------------------------------------
__global__ __launch_bounds__(256)
void scatter_kernel(const int*   __restrict__ erow,
                    const int*   __restrict__ ecol,
                    const float* __restrict__ eval,
                    int E) {
    const int e = blockIdx.x * 256 + threadIdx.x;
    if (e >= E) return;
    const int row  = erow[e];
    const int base = g_lex[row] + g_part[row >> 8];
    const int ofs  = atomicAdd(&g_cur[row], 1);
    g_pairs[base + ofs] = make_int2(ecol[e], __float_as_int(eval[e]));
}

// ---------------------------------------------------------------------------
// K5: warp-per-row gather + fused PReLU. Lane owns cols (2*lane, 2*lane+1).
// Edge pairs read with a warp-uniform LDG (broadcast), unrolled x2.
// ---------------------------------------------------------------------------
__global__ __launch_bounds__(256)
void gather_kernel(float* __restrict__ out,
                   const float* __restrict__ alpha,
                   int N) {
    const int lane = threadIdx.x & 31;
    const int row  = blockIdx.x * 8 + (threadIdx.x >> 5);
    if (row >= N) return;

    const int start = g_lex[row]     + g_part[row >> 8];
    const int end   = g_lex[row + 1] + g_part[(row + 1) >> 8];

    float2 acc = make_float2(0.f, 0.f);
    const float2* __restrict__ h2 = reinterpret_cast<const float2*>(g_h);

    int j = start;
    for (; j + 1 < end; j += 2) {
        const int2 p0 = __ldg(&g_pairs[j]);
        const int2 p1 = __ldg(&g_pairs[j + 1]);
        const float2 a0 = __ldg(&h2[(size_t)p0.x * 32 + lane]);
        const float2 a1 = __ldg(&h2[(size_t)p1.x * 32 + lane]);
        const float v0 = __int_as_float(p0.y);
        const float v1 = __int_as_float(p1.y);
        acc.x = fmaf(v0, a0.x, acc.x);
        acc.y = fmaf(v0, a0.y, acc.y);
        acc.x = fmaf(v1, a1.x, acc.x);
        acc.y = fmaf(v1, a1.y, acc.y);
    }
    if (j < end) {
        const int2 p = __ldg(&g_pairs[j]);
        const float2 a = __ldg(&h2[(size_t)p.x * 32 + lane]);
        const float v = __int_as_float(p.y);
        acc.x = fmaf(v, a.x, acc.x);
        acc.y = fmaf(v, a.y, acc.y);
    }

    const float al = __ldg(alpha);
    acc.x = acc.x >= 0.f ? acc.x : al * acc.x;
    acc.y = acc.y >= 0.f ? acc.y : al * acc.y;
    reinterpret_cast<float2*>(out)[(size_t)row * 32 + lane] = acc;
}

// ---------------------------------------------------------------------------
// Launch. Inputs: x, W, b, alpha, edge_row, edge_col, edge_val
// ---------------------------------------------------------------------------
extern "C" void kernel_launch(void* const* d_in, const int* in_sizes, int n_in,
                              void* d_out, int out_size) {
    const float* x     = (const float*)d_in[0];
    const float* W     = (const float*)d_in[1];
    const float* b     = (const float*)d_in[2];
    const float* alpha = (const float*)d_in[3];
    const int*   erow  = (const int*)  d_in[4];
    const int*   ecol  = (const int*)  d_in[5];
    const float* eval  = (const float*)d_in[6];

    const int N  = in_sizes[0] / IN_FT;
    const int E  = in_sizes[4];
    const int NB = (N + 256) / 256;   // covers idx N; must be <= NB_CAP
    float* out = (float*)d_out;

    gemm_hist_kernel<<<(N + 63) / 64, 128>>>(x, W, b, erow, N, E);
    scanB_kernel<<<NB, 256>>>(N);
    scanP_kernel<<<1, NB_CAP>>>(NB);
    scatter_kernel<<<(E + 255) / 256, 256>>>(erow, ecol, eval, E);
    gather_kernel<<<(N + 7) / 8, 256>>>(out, alpha, N);
}